// round 11
// baseline (speedup 1.0000x reference)
#include <cuda_runtime.h>

#define BATCH   128
#define LSIG    128000
#define NFFT    1024
#define HOP     320
#define NMELS   128
#define NFRAMES 401
#define NFREQ   513
#define MAXW    28
#define PI_D    3.14159265358979323846

typedef unsigned long long u64;

// ---------------- device globals (no allocations allowed) -------------------
__device__ float2 g_win2[512];                 // (w[2n], w[2n+1]) interleaved hann
__device__ float2 g_tw[512];                   // W_1024^k
__device__ float2 g_tw512[512];                // W_512^k
__device__ int    g_mlo[NMELS];
__device__ int    g_mlen[NMELS];
__device__ float  g_fbw[MAXW][NMELS];          // zero-padded rows
__device__ float  g_mel[BATCH * NFRAMES * NMELS];

// ---------------- packed f32x2 helpers (Blackwell) ---------------------------
__device__ __forceinline__ u64 pk2(float a, float b) {
    u64 r; asm("mov.b64 %0,{%1,%2};" : "=l"(r) : "f"(a), "f"(b)); return r;
}
__device__ __forceinline__ float2 upk2(u64 a) {
    float2 r; asm("mov.b64 {%0,%1},%2;" : "=f"(r.x), "=f"(r.y) : "l"(a)); return r;
}
__device__ __forceinline__ u64 fadd2_(u64 a, u64 b) {
    u64 r; asm("add.rn.f32x2 %0,%1,%2;" : "=l"(r) : "l"(a), "l"(b)); return r;
}
__device__ __forceinline__ u64 fmul2_(u64 a, u64 b) {
    u64 r; asm("mul.rn.f32x2 %0,%1,%2;" : "=l"(r) : "l"(a), "l"(b)); return r;
}
__device__ __forceinline__ u64 ffma2_(u64 a, u64 b, u64 c) {
    u64 r; asm("fma.rn.f32x2 %0,%1,%2,%3;" : "=l"(r) : "l"(a), "l"(b), "l"(c)); return r;
}
// a - b == fma(b, -1, a): exact, single op, avoids relying on sub.f32x2
__device__ __forceinline__ u64 fsub2_(u64 a, u64 b) {
    return ffma2_(b, 0xBF800000BF800000ULL, a);
}

struct cx { u64 re, im; };

// packed 8-point DFT: two frames in the .lo/.hi lanes of every u64
__device__ __forceinline__ void dft8p(cx v[8]) {
    const u64 C2 = 0x3F3504F33F3504F3ULL;      // (0.70710678f, 0.70710678f)
    cx s0 = {fadd2_(v[0].re, v[4].re), fadd2_(v[0].im, v[4].im)};
    cx d0 = {fsub2_(v[0].re, v[4].re), fsub2_(v[0].im, v[4].im)};
    cx s1 = {fadd2_(v[2].re, v[6].re), fadd2_(v[2].im, v[6].im)};
    cx d1 = {fsub2_(v[2].re, v[6].re), fsub2_(v[2].im, v[6].im)};
    cx s2 = {fadd2_(v[1].re, v[5].re), fadd2_(v[1].im, v[5].im)};
    cx d2 = {fsub2_(v[1].re, v[5].re), fsub2_(v[1].im, v[5].im)};
    cx s3 = {fadd2_(v[3].re, v[7].re), fadd2_(v[3].im, v[7].im)};
    cx d3 = {fsub2_(v[3].re, v[7].re), fsub2_(v[3].im, v[7].im)};
    cx e0 = {fadd2_(s0.re, s1.re), fadd2_(s0.im, s1.im)};
    cx e2 = {fsub2_(s0.re, s1.re), fsub2_(s0.im, s1.im)};
    cx e1 = {fadd2_(d0.re, d1.im), fsub2_(d0.im, d1.re)};   // d0 + (-i)d1
    cx e3 = {fsub2_(d0.re, d1.im), fadd2_(d0.im, d1.re)};   // d0 - (-i)d1
    cx o0 = {fadd2_(s2.re, s3.re), fadd2_(s2.im, s3.im)};
    cx o2 = {fsub2_(s2.re, s3.re), fsub2_(s2.im, s3.im)};
    cx o1 = {fadd2_(d2.re, d3.im), fsub2_(d2.im, d3.re)};
    cx o3 = {fsub2_(d2.re, d3.im), fadd2_(d2.im, d3.re)};
    u64 t1r = fmul2_(C2, fadd2_(o1.re, o1.im));
    u64 t1i = fmul2_(C2, fsub2_(o1.im, o1.re));
    u64 t3r = fmul2_(C2, fsub2_(o3.im, o3.re));
    u64 u3  = fmul2_(C2, fadd2_(o3.re, o3.im));
    v[0].re = fadd2_(e0.re, o0.re);  v[0].im = fadd2_(e0.im, o0.im);
    v[4].re = fsub2_(e0.re, o0.re);  v[4].im = fsub2_(e0.im, o0.im);
    v[1].re = fadd2_(e1.re, t1r);    v[1].im = fadd2_(e1.im, t1i);
    v[5].re = fsub2_(e1.re, t1r);    v[5].im = fsub2_(e1.im, t1i);
    v[2].re = fadd2_(e2.re, o2.im);  v[2].im = fsub2_(e2.im, o2.re);
    v[6].re = fsub2_(e2.re, o2.im);  v[6].im = fadd2_(e2.im, o2.re);
    v[3].re = fadd2_(e3.re, t3r);    v[3].im = fsub2_(e3.im, u3);
    v[7].re = fsub2_(e3.re, t3r);    v[7].im = fadd2_(e3.im, u3);
}

__device__ __forceinline__ void cmulp(cx &a, u64 wx, u64 wy) {
    u64 nre = fsub2_(fmul2_(a.re, wx), fmul2_(a.im, wy));
    u64 nim = ffma2_(a.re, wy, fmul2_(a.im, wx));
    a.re = nre; a.im = nim;
}

#define PAD(i) ((i) + ((i) >> 3))   // max PAD(519)=583 < 592

// ---------------- init: fully parallel (unchanged from R10) ------------------
__global__ void init_kernel() {
    const int bx = blockIdx.x, tid = threadIdx.x;

    if (bx < NMELS) {
        __shared__ double sf[3];
        __shared__ double si01, si12;
        __shared__ int s_lo, s_hi;
        if (tid == 0) { s_lo = 1 << 30; s_hi = -1; }
        if (tid < 3) {
            double mel_max = 2595.0 * log10(1.0 + 16000.0 / 700.0);
            sf[tid] = 700.0 * (exp10((mel_max * (double)(bx + tid) / 129.0) / 2595.0) - 1.0);
        }
        __syncthreads();
        if (tid == 0) { si01 = 1.0 / (sf[1] - sf[0]); si12 = 1.0 / (sf[2] - sf[1]); }
        __syncthreads();

        double wgt = -1.0;
        if (tid < NFREQ) {
            double freq = (double)tid * (16000.0 / 512.0);
            wgt = fmin((freq - sf[0]) * si01, (sf[2] - freq) * si12);
            if (wgt > 0.0) { atomicMin(&s_lo, tid); atomicMax(&s_hi, tid); }
        }
        __syncthreads();
        int lo = s_lo, hi = s_hi;
        int len = (hi < 0) ? 0 : (hi - lo + 1);
        if (len > MAXW) len = MAXW;
        if (tid == 0) { g_mlo[bx] = (hi < 0) ? 0 : lo; g_mlen[bx] = len; }
        if (wgt > 0.0) {
            int i = tid - lo;
            if (i >= 0 && i < MAXW) g_fbw[i][bx] = (float)wgt;
        }
        if (tid < MAXW && tid >= len) g_fbw[tid][bx] = 0.0f;
    } else {
        int i = (bx - NMELS) * 64 + tid;
        if (tid < 64 && i < 512) {
            float w0 = 0.5f * (1.0f - cospif((float)(2 * i)     * (1.0f / 512.0f)));
            float w1 = 0.5f * (1.0f - cospif((float)(2 * i + 1) * (1.0f / 512.0f)));
            g_win2[i] = make_float2(w0, w1);
            float s, c;
            sincospif((float)i * (-1.0f / 512.0f), &s, &c);
            g_tw[i] = make_float2(c, s);
            float s2, c2;
            sincospif((float)i * (-1.0f / 256.0f), &s2, &c2);
            g_tw512[i] = make_float2(c2, s2);
        }
    }
}

// ---------------- mel spectrogram: TWO frames per warp, packed f32x2 ---------
__global__ __launch_bounds__(128) void melspec_kernel(const float* __restrict__ x) {
    __shared__ u64 bre[4][592];                 // re plane: (frameA, frameB)
    __shared__ u64 bim[4][592];                 // im plane
    __shared__ u64 swx[512];                    // (wx,wx) broadcast pairs, W_512
    __shared__ u64 swy[512];                    // (wy,wy)

    const int tid  = threadIdx.x;
    const int w    = tid >> 5;
    const int lane = tid & 31;

    #pragma unroll
    for (int r = 0; r < 4; r++) {
        int i = tid + 128 * r;
        float2 tw = g_tw512[i];
        swx[i] = pk2(tw.x, tw.x);
        swy[i] = pk2(tw.y, tw.y);
    }
    __syncthreads();

    const int fr = (blockIdx.x * 4 + w) * 2;    // frame A index
    const bool validA = (fr     < NFRAMES);
    const bool validB = (fr + 1 < NFRAMES);
    const int tA = validA ? fr     : NFRAMES - 1;
    const int tB = validB ? fr + 1 : NFRAMES - 1;
    const int b  = blockIdx.y;

    const float* __restrict__ xb = x + (long long)b * LSIG;
    const int baseA = tA * HOP - 512;
    const int baseB = tB * HOP - 512;
    const bool fast = (baseA >= 0) && (baseB + NFFT <= LSIG);

    // ---- stage 0 fused with load: out[8vt+k] = DFT8_k * W512^{vt*k}
    #pragma unroll
    for (int h = 0; h < 2; h++) {
        const int vt = lane + 32 * h;
        cx v[8];
        if (fast) {
            const float2* __restrict__ xA = (const float2*)(xb + baseA);
            const float2* __restrict__ xB = (const float2*)(xb + baseB);
            #pragma unroll
            for (int j = 0; j < 8; j++) {
                int n = vt + 64 * j;
                float2 sa = xA[n], sb = xB[n], wn = g_win2[n];
                v[j].re = pk2(sa.x * wn.x, sb.x * wn.x);
                v[j].im = pk2(sa.y * wn.y, sb.y * wn.y);
            }
        } else {
            #pragma unroll
            for (int j = 0; j < 8; j++) {
                int n = vt + 64 * j;
                int a0 = baseA + 2 * n, a1 = a0 + 1;
                int b0 = baseB + 2 * n, b1 = b0 + 1;
                a0 = a0 < 0 ? -a0 : (a0 >= LSIG ? 2 * LSIG - 2 - a0 : a0);
                a1 = a1 < 0 ? -a1 : (a1 >= LSIG ? 2 * LSIG - 2 - a1 : a1);
                b0 = b0 < 0 ? -b0 : (b0 >= LSIG ? 2 * LSIG - 2 - b0 : b0);
                b1 = b1 < 0 ? -b1 : (b1 >= LSIG ? 2 * LSIG - 2 - b1 : b1);
                float2 wn = g_win2[n];
                v[j].re = pk2(xb[a0] * wn.x, xb[b0] * wn.x);
                v[j].im = pk2(xb[a1] * wn.y, xb[b1] * wn.y);
            }
        }
        dft8p(v);
        #pragma unroll
        for (int k = 1; k < 8; k++) cmulp(v[k], swx[vt * k], swy[vt * k]);
        #pragma unroll
        for (int k = 0; k < 8; k++) {
            int P = PAD(8 * vt + k);
            bre[w][P] = v[k].re; bim[w][P] = v[k].im;
        }
    }
    __syncwarp();

    // ---- stage 1: out[64p + q + 8k] = DFT8_k * W512^{8pk}
    {
        cx v2[2][8];
        #pragma unroll
        for (int h = 0; h < 2; h++)
        #pragma unroll
        for (int j = 0; j < 8; j++) {
            int P = PAD(lane + 32 * h + 64 * j);
            v2[h][j].re = bre[w][P]; v2[h][j].im = bim[w][P];
        }
        __syncwarp();
        #pragma unroll
        for (int h = 0; h < 2; h++) {
            int vt = lane + 32 * h, p = vt >> 3, q = vt & 7;
            dft8p(v2[h]);
            #pragma unroll
            for (int k = 1; k < 8; k++) cmulp(v2[h][k], swx[8 * p * k], swy[8 * p * k]);
            #pragma unroll
            for (int k = 0; k < 8; k++) {
                int P = PAD(64 * p + q + 8 * k);
                bre[w][P] = v2[h][k].re; bim[w][P] = v2[h][k].im;
            }
        }
    }
    __syncwarp();

    // ---- stage 2: out[vt + 64k] = DFT8_k (no twiddle)
    {
        cx v2[2][8];
        #pragma unroll
        for (int h = 0; h < 2; h++)
        #pragma unroll
        for (int j = 0; j < 8; j++) {
            int P = PAD(lane + 32 * h + 64 * j);
            v2[h][j].re = bre[w][P]; v2[h][j].im = bim[w][P];
        }
        __syncwarp();
        #pragma unroll
        for (int h = 0; h < 2; h++) {
            int vt = lane + 32 * h;
            dft8p(v2[h]);
            #pragma unroll
            for (int k = 0; k < 8; k++) {
                int P = PAD(vt + 64 * k);
                bre[w][P] = v2[h][k].re; bim[w][P] = v2[h][k].im;
            }
        }
    }
    __syncwarp();

    // ---- conjugate-pair unpack, in place at OWNED padded slots:
    //   X[k] = E + W*O,  X[512-k] = conj(E - W*O); pairs (k,512-k) partition
    //   0..511 one-owner-per-slot, so no cross-thread write hazard.
    const u64 HALF = 0x3F0000003F000000ULL;     // (0.5f, 0.5f)
    #pragma unroll
    for (int u = 0; u < 8; u++) {
        int k  = lane + 32 * (u & 1) + 64 * (u >> 1);   // 0..255
        int Pk = PAD(k), Pr = PAD((512 - k) & 511);
        u64 zkr = bre[w][Pk], zki = bim[w][Pk];
        u64 zrr = bre[w][Pr], zri = bim[w][Pr];
        u64 ex = fmul2_(HALF, fadd2_(zkr, zrr));
        u64 ey = fmul2_(HALF, fsub2_(zki, zri));
        u64 ox = fmul2_(HALF, fadd2_(zki, zri));
        u64 oy = fmul2_(HALF, fsub2_(zrr, zkr));
        float2 tw = __ldg(&g_tw[k]);
        u64 twx = pk2(tw.x, tw.x), twy = pk2(tw.y, tw.y);
        u64 wox = fsub2_(fmul2_(ox, twx), fmul2_(oy, twy));
        u64 woy = ffma2_(ox, twy, fmul2_(oy, twx));
        float2 ar = upk2(fadd2_(ex, wox)), ai = upk2(fadd2_(ey, woy));
        float2 br = upk2(fsub2_(ex, wox)), bi = upk2(fsub2_(ey, woy));
        bre[w][Pk] = pk2(sqrtf(ar.x * ar.x + ai.x * ai.x),
                         sqrtf(ar.y * ar.y + ai.y * ai.y));
        bre[w][PAD(512 - k)] = pk2(sqrtf(br.x * br.x + bi.x * bi.x),
                                   sqrtf(br.y * br.y + bi.y * bi.y));
    }
    if (lane == 0) {
        float2 zr = upk2(bre[w][PAD(256)]), zi = upk2(bim[w][PAD(256)]);
        bre[w][PAD(256)] = pk2(sqrtf(zr.x * zr.x + zi.x * zi.x),
                               sqrtf(zr.y * zr.y + zi.y * zi.y));
        #pragma unroll
        for (int q2 = 513; q2 < 520; q2++) bre[w][PAD(q2)] = 0ULL;
    }
    __syncwarp();

    // ---- mel gather (packed): both frames per FMA
    if (validA) {
        float* __restrict__ omA = g_mel + ((long long)b * NFRAMES + tA) * NMELS;
        float* __restrict__ omB = g_mel + ((long long)b * NFRAMES + tB) * NMELS;
        #pragma unroll
        for (int g = 0; g < 4; g++) {
            int m    = lane + 32 * g;
            int lo   = g_mlo[m];
            int len4 = (g_mlen[m] + 3) & ~3;
            const float* __restrict__ wm = &g_fbw[0][m];
            u64 a0 = 0ULL, a1 = 0ULL, a2 = 0ULL, a3 = 0ULL;
            for (int i = 0; i < len4; i += 4) {
                float w0 = wm[(i    ) * NMELS];
                float w1 = wm[(i + 1) * NMELS];
                float w2 = wm[(i + 2) * NMELS];
                float w3 = wm[(i + 3) * NMELS];
                a0 = ffma2_(bre[w][PAD(lo + i    )], pk2(w0, w0), a0);
                a1 = ffma2_(bre[w][PAD(lo + i + 1)], pk2(w1, w1), a1);
                a2 = ffma2_(bre[w][PAD(lo + i + 2)], pk2(w2, w2), a2);
                a3 = ffma2_(bre[w][PAD(lo + i + 3)], pk2(w3, w3), a3);
            }
            float2 s = upk2(fadd2_(fadd2_(a0, a1), fadd2_(a2, a3)));
            omA[m] = s.x;
            if (validB) omB[m] = s.y;
        }
    }
}

// ---------------- PCEN: 8-chunk parallel IIR (unchanged from R10) ------------
#define NCHUNK 8
#define CHLEN  51
__global__ __launch_bounds__(1024) void pcen_kernel(float* __restrict__ out) {
    const int b   = blockIdx.x;
    const int tid = threadIdx.x;
    const int c   = tid >> 7;
    const int m   = tid & 127;

    const int t0 = c * CHLEN;
    const int t1 = (t0 + CHLEN > NFRAMES) ? NFRAMES : t0 + CHLEN;

    const float* __restrict__ mel = g_mel + (long long)b * NFRAMES * NMELS;
    float* __restrict__ obase = out + (long long)b * NMELS * NFRAMES;

    const float a1c = 0.975f, s0 = 0.025f;
    const float sqrt2 = 1.41421356237309515f;

    __shared__ float sA[NCHUNK][NMELS];
    __shared__ float sB[NCHUNK][NMELS];
    __shared__ float sMin[NCHUNK][NMELS];

    if (c == 0) {
        float M = mel[m];
        for (int t = 1; t < t1; t++)
            M = fmaf(a1c, M, s0 * mel[t * NMELS + m]);
        sA[0][m] = 0.0f; sB[0][m] = M;
    } else {
        float B = 0.0f;
        for (int t = t0; t < t1; t++)
            B = fmaf(a1c, B, s0 * mel[t * NMELS + m]);
        sA[c][m] = __powf(a1c, (float)(t1 - t0));
        sB[c][m] = B;
    }
    __syncthreads();

    if (tid < NMELS) {
        float e = sB[0][tid];
        sMin[0][tid] = 0.0f;
        sMin[1][tid] = e;
        #pragma unroll
        for (int cc = 1; cc < NCHUNK - 1; cc++) {
            e = fmaf(sA[cc][tid], e, sB[cc][tid]);
            sMin[cc + 1][tid] = e;
        }
    }
    __syncthreads();

    float M = sMin[c][m];
    float sum = 0.0f, cs = 0.0f, sq = 0.0f, cq = 0.0f;
    for (int t = t0; t < t1; t++) {
        float xv = mel[t * NMELS + m];
        M = (c == 0 && t == 0) ? xv : fmaf(a1c, M, s0 * xv);
        float z = 1e-6f + M;
        float u = fmaf(xv, __powf(z, -0.98f), 2.0f);
        float p = u * rsqrtf(u) - sqrt2;
        obase[m * NFRAMES + t] = p;
        float y = p - cs, tn = sum + y; cs = (tn - sum) - y; sum = tn;
        float pp = p * p;
        float y2 = pp - cq, tq = sq + y2; cq = (tq - sq) - y2; sq = tq;
    }

    __shared__ double dsum[1024];
    __shared__ double dsq[1024];
    __shared__ float  s_mean, s_inv;
    dsum[tid] = (double)sum + (double)cs;
    dsq[tid]  = (double)sq  + (double)cq;
    __syncthreads();
    for (int o = 512; o > 0; o >>= 1) {
        if (tid < o) { dsum[tid] += dsum[tid + o]; dsq[tid] += dsq[tid + o]; }
        __syncthreads();
    }
    if (tid == 0) {
        const double n = (double)(NMELS * NFRAMES);
        double mean = dsum[0] / n;
        double var  = (dsq[0] - dsum[0] * dsum[0] / n) / (n - 1.0);
        if (var < 0.0) var = 0.0;
        s_mean = (float)mean;
        s_inv  = (float)(1.0 / (sqrt(var) + 1e-6));
    }
    __syncthreads();

    float mean = s_mean, inv = s_inv;
    float4* o4 = (float4*)obase;
    const int tot4 = NMELS * NFRAMES / 4;
    for (int i = tid; i < tot4; i += 1024) {
        float4 v = o4[i];
        v.x = (v.x - mean) * inv;
        v.y = (v.y - mean) * inv;
        v.z = (v.z - mean) * inv;
        v.w = (v.w - mean) * inv;
        o4[i] = v;
    }
}

// ---------------- launch ------------------------------------------------------
extern "C" void kernel_launch(void* const* d_in, const int* in_sizes, int n_in,
                              void* d_out, int out_size) {
    const float* x = (const float*)d_in[0];
    float* out = (float*)d_out;

    init_kernel<<<NMELS + 8, 544>>>();
    melspec_kernel<<<dim3((NFRAMES + 7) / 8, BATCH), 128>>>(x);
    pcen_kernel<<<BATCH, 1024>>>(out);
}